// round 2
// baseline (speedup 1.0000x reference)
#include <cuda_runtime.h>

#define BB 4
#define NN 16384
#define NC 1024
#define KK 32

// ---------------- scratch (device globals; no allocation allowed) ----------------
__device__ int           g_cent_idx[BB][NC];
__device__ int           g_cent_cnt[BB];
__device__ unsigned char g_flag[BB][NN];
__device__ int           g_list[BB][NN];
__device__ int           g_list_cnt[BB];
__device__ float         g_feat[BB * 1024];   // max-pooled (relu'd) features

// ---------------- helpers ----------------
__device__ __forceinline__ unsigned long long dkey(float d, int idx) {
    unsigned u = __float_as_uint(d);
    u = (u & 0x80000000u) ? ~u : (u | 0x80000000u);   // ascending-sortable
    return ((unsigned long long)u << 32) | (unsigned)idx;
}

__device__ __forceinline__ void warp_max(unsigned long long key, int lane,
                                         unsigned long long& mk, int& ml) {
    unsigned long long v = key; int l = lane;
    #pragma unroll
    for (int off = 16; off; off >>= 1) {
        unsigned long long v2 = __shfl_xor_sync(0xffffffffu, v, off);
        int l2 = __shfl_xor_sync(0xffffffffu, l, off);
        if (v2 > v) { v = v2; l = l2; }
    }
    mk = v; ml = l;
}

// ---------------- zero scratch ----------------
__global__ void zero_kernel() {
    int i = blockIdx.x * blockDim.x + threadIdx.x;
    if (i < (BB * NN) / 4) ((unsigned*)g_flag)[i] = 0u;
    if (i < BB * 1024)     g_feat[i] = 0.0f;
    if (i < BB)            g_list_cnt[i] = 0;
}

// ---------------- FPS walk with cycle detection (1 block per batch) ----------------
__global__ __launch_bounds__(1024) void fps_kernel(const float* __restrict__ x,
                                                   const int* __restrict__ far_init) {
    const int b = blockIdx.x;
    const float* xb = x + (size_t)b * NN * 3;
    __shared__ unsigned char seen[NN];
    __shared__ float s_d[32];
    __shared__ int   s_i[32];
    __shared__ int   s_far, s_stop, s_cnt;
    const int t = threadIdx.x;

    for (int i = t; i < NN; i += 1024) seen[i] = 0;
    if (t == 0) s_cnt = 0;
    __syncthreads();

    int far = far_init[b];
    for (int it = 0; it < NC; ++it) {
        if (t == 0) {
            if (seen[far]) { s_stop = 1; }
            else { seen[far] = 1; g_cent_idx[b][s_cnt] = far; s_cnt++; s_stop = 0; }
        }
        __syncthreads();
        if (s_stop) break;
        if (it == NC - 1) break;

        const float cx = xb[far * 3 + 0], cy = xb[far * 3 + 1], cz = xb[far * 3 + 2];
        float best = -1.0f; int bi = 0;
        for (int n = t; n < NN; n += 1024) {
            float dx = xb[n * 3 + 0] - cx;
            float dy = xb[n * 3 + 1] - cy;
            float dz = xb[n * 3 + 2] - cz;
            float d = dx * dx + dy * dy + dz * dz;
            if (d > best) { best = d; bi = n; }   // strict > keeps lowest index on ties
        }
        #pragma unroll
        for (int off = 16; off; off >>= 1) {
            float d2 = __shfl_xor_sync(0xffffffffu, best, off);
            int   i2 = __shfl_xor_sync(0xffffffffu, bi, off);
            if (d2 > best || (d2 == best && i2 < bi)) { best = d2; bi = i2; }
        }
        if ((t & 31) == 0) { s_d[t >> 5] = best; s_i[t >> 5] = bi; }
        __syncthreads();
        if (t < 32) {
            best = s_d[t]; bi = s_i[t];
            #pragma unroll
            for (int off = 16; off; off >>= 1) {
                float d2 = __shfl_xor_sync(0xffffffffu, best, off);
                int   i2 = __shfl_xor_sync(0xffffffffu, bi, off);
                if (d2 > best || (d2 == best && i2 < bi)) { best = d2; bi = i2; }
            }
            if (t == 0) s_far = bi;
        }
        __syncthreads();
        far = s_far;
    }
    if (t == 0) g_cent_cnt[b] = s_cnt;
}

// ---------------- exact warp-resident top-K (K==32), one warp per centroid --------
__global__ __launch_bounds__(256) void knn_kernel(const float* __restrict__ x) {
    const int wglobal = (blockIdx.x * blockDim.x + threadIdx.x) >> 5;
    const int lane = threadIdx.x & 31;
    const int b = wglobal / NC;
    const int m = wglobal % NC;
    if (b >= BB) return;
    if (m >= g_cent_cnt[b]) return;

    const float* xb = x + (size_t)b * NN * 3;
    const int ci = g_cent_idx[b][m];
    const float cx = xb[ci * 3 + 0], cy = xb[ci * 3 + 1], cz = xb[ci * 3 + 2];
    const float cn = cx * cx + cy * cy + cz * cz;

    unsigned long long key;
    {
        const int p = lane;
        float px = xb[p * 3 + 0], py = xb[p * 3 + 1], pz = xb[p * 3 + 2];
        float xn = px * px + py * py + pz * pz;
        float dot = cx * px + cy * py + cz * pz;
        float d2 = (cn + xn) - 2.0f * dot;     // matches reference formula order
        key = dkey(d2, p);
    }
    unsigned long long mk; int ml;
    warp_max(key, lane, mk, ml);

    for (int base = 32; base < NN; base += 32) {
        const int p = base + lane;
        float px = xb[p * 3 + 0], py = xb[p * 3 + 1], pz = xb[p * 3 + 2];
        float xn = px * px + py * py + pz * pz;
        float dot = cx * px + cy * py + cz * pz;
        float d2 = (cn + xn) - 2.0f * dot;
        unsigned long long k = dkey(d2, p);
        unsigned mask = __ballot_sync(0xffffffffu, k < mk);
        while (mask) {
            const int src = __ffs(mask) - 1;
            mask &= mask - 1;
            unsigned long long kc = __shfl_sync(0xffffffffu, k, src);
            if (kc < mk) {                 // uniform: kc, mk warp-uniform
                if (lane == ml) key = kc;  // replace current max slot
                warp_max(key, lane, mk, ml);
            }
        }
    }
    g_flag[b][(int)(key & 0xffffffffull)] = 1;
}

// ---------------- compact flagged union set ----------------
__global__ void compact_kernel() {
    const int b = blockIdx.x;
    for (int n = threadIdx.x; n < NN; n += blockDim.x) {
        if (g_flag[b][n]) {
            int pos = atomicAdd(&g_list_cnt[b], 1);
            g_list[b][pos] = n;
        }
    }
}

// ---------------- fused MLP(3->64->64->64->128->1024) + relu + block-local max ----
__global__ __launch_bounds__(128) void mlp_kernel(
    const float* __restrict__ x,
    const float* __restrict__ w1, const float* __restrict__ b1,
    const float* __restrict__ w2, const float* __restrict__ b2,
    const float* __restrict__ w3, const float* __restrict__ b3,
    const float* __restrict__ w4, const float* __restrict__ b4,
    const float* __restrict__ w5, const float* __restrict__ b5) {
    __shared__ float h1[64], h2[64], h3[64], h4[128];
    const int t = threadIdx.x;

    for (int b = 0; b < BB; ++b) {
        const int cnt = g_list_cnt[b];
        float rmax[8];
        #pragma unroll
        for (int j = 0; j < 8; ++j) rmax[j] = 0.0f;

        for (int i = blockIdx.x; i < cnt; i += gridDim.x) {
            const int n = g_list[b][i];
            const float* p = x + ((size_t)b * NN + n) * 3;
            const float px = p[0], py = p[1], pz = p[2];

            if (t < 64) {
                float a = b1[t] + w1[t * 3 + 0] * px + w1[t * 3 + 1] * py + w1[t * 3 + 2] * pz;
                h1[t] = fmaxf(a, 0.0f);
            }
            __syncthreads();
            if (t < 64) {
                float a = b2[t];
                const float* w = w2 + t * 64;
                #pragma unroll 8
                for (int k = 0; k < 64; ++k) a += w[k] * h1[k];
                h2[t] = fmaxf(a, 0.0f);
            }
            __syncthreads();
            if (t < 64) {
                float a = b3[t];
                const float* w = w3 + t * 64;
                #pragma unroll 8
                for (int k = 0; k < 64; ++k) a += w[k] * h2[k];
                h3[t] = fmaxf(a, 0.0f);
            }
            __syncthreads();
            {
                float a = b4[t];
                const float* w = w4 + t * 64;
                #pragma unroll 8
                for (int k = 0; k < 64; ++k) a += w[k] * h3[k];
                h4[t] = fmaxf(a, 0.0f);
            }
            __syncthreads();
            #pragma unroll
            for (int j = 0; j < 8; ++j) {
                const int o = t + j * 128;
                const float* w = w5 + o * 128;
                float acc = 0.0f;
                #pragma unroll 8
                for (int k = 0; k < 128; ++k) acc += w[k] * h4[k];
                float v = fmaxf(b5[o] + acc, 0.0f);
                rmax[j] = fmaxf(rmax[j], v);
            }
            __syncthreads();
        }
        #pragma unroll
        for (int j = 0; j < 8; ++j) {
            atomicMax((unsigned int*)&g_feat[b * 1024 + t + j * 128],
                      __float_as_uint(rmax[j]));   // valid: all values >= 0
        }
    }
}

// ---------------- final FC head ----------------
__global__ __launch_bounds__(512) void fc_kernel(
    const float* __restrict__ fw1, const float* __restrict__ fb1,
    const float* __restrict__ fw2, const float* __restrict__ fb2,
    const float* __restrict__ fw3, const float* __restrict__ fb3,
    float* __restrict__ out) {
    __shared__ float g[1024], a1[512], a2[256];
    const int t = threadIdx.x;
    for (int b = 0; b < BB; ++b) {
        for (int i = t; i < 1024; i += 512) g[i] = g_feat[b * 1024 + i];
        __syncthreads();
        {
            float a = fb1[t];
            const float* w = fw1 + t * 1024;
            #pragma unroll 8
            for (int k = 0; k < 1024; ++k) a += w[k] * g[k];
            a1[t] = fmaxf(a, 0.0f);
        }
        __syncthreads();
        if (t < 256) {
            float a = fb2[t];
            const float* w = fw2 + t * 512;
            #pragma unroll 8
            for (int k = 0; k < 512; ++k) a += w[k] * a1[k];
            a2[t] = fmaxf(a, 0.0f);
        }
        __syncthreads();
        if (t < 3) {
            float a = fb3[t];
            const float* w = fw3 + t * 256;
            for (int k = 0; k < 256; ++k) a += w[k] * a2[k];
            out[b * 3 + t] = a;
        }
        __syncthreads();
    }
}

// ---------------- launch ----------------
extern "C" void kernel_launch(void* const* d_in, const int* in_sizes, int n_in,
                              void* d_out, int out_size) {
    const float* x   = (const float*)d_in[0];
    const int*   far = (const int*)  d_in[1];
    const float* w1 = (const float*)d_in[2];   const float* b1 = (const float*)d_in[3];
    const float* w2 = (const float*)d_in[4];   const float* b2 = (const float*)d_in[5];
    const float* w3 = (const float*)d_in[6];   const float* b3 = (const float*)d_in[7];
    const float* w4 = (const float*)d_in[8];   const float* b4 = (const float*)d_in[9];
    const float* w5 = (const float*)d_in[10];  const float* b5 = (const float*)d_in[11];
    const float* fw1 = (const float*)d_in[12]; const float* fb1 = (const float*)d_in[13];
    const float* fw2 = (const float*)d_in[14]; const float* fb2 = (const float*)d_in[15];
    const float* fw3 = (const float*)d_in[16]; const float* fb3 = (const float*)d_in[17];
    float* out = (float*)d_out;

    zero_kernel<<<64, 256>>>();
    fps_kernel<<<BB, 1024>>>(x, far);
    knn_kernel<<<(BB * NC * 32) / 256, 256>>>(x);
    compact_kernel<<<BB, 256>>>();
    mlp_kernel<<<512, 128>>>(x, w1, b1, w2, b2, w3, b3, w4, b4, w5, b5);
    fc_kernel<<<1, 512>>>(fw1, fb1, fw2, fb2, fw3, fb3, out);
}

// round 4
// speedup vs baseline: 11.1275x; 11.1275x over previous
#include <cuda_runtime.h>

#define BB 4
#define NN 16384
#define NC 1024

// ---------------- scratch (device globals; no allocation allowed) ----------------
__device__ int          g_cent_idx[BB][NC];
__device__ int          g_cent_cnt[BB];
__device__ unsigned int g_flagw[BB][NN / 4];
__device__ int          g_list[BB][NN];
__device__ int          g_list_cnt[BB];
__device__ float        g_feat[BB * 1024];           // max-pooled (relu'd) features
__device__ float        g_h4[BB][NN][128];           // per-point layer-4 activations
__device__ float        g_tw1[3 * 64];               // transposed small weights
__device__ float        g_tw2[64 * 64];
__device__ float        g_tw3[64 * 64];
__device__ float        g_tw4[64 * 128];

// ---------------- helpers ----------------
__device__ __forceinline__ unsigned long long dkey(float d, int idx) {
    unsigned u = __float_as_uint(d);
    u = (u & 0x80000000u) ? ~u : (u | 0x80000000u);   // ascending-sortable
    return ((unsigned long long)u << 32) | (unsigned)idx;
}

__device__ __forceinline__ void warp_max(unsigned long long key, int lane,
                                         unsigned long long& mk, int& ml) {
    unsigned long long v = key; int l = lane;
    #pragma unroll
    for (int off = 16; off; off >>= 1) {
        unsigned long long v2 = __shfl_xor_sync(0xffffffffu, v, off);
        int l2 = __shfl_xor_sync(0xffffffffu, l, off);
        if (v2 > v) { v = v2; l = l2; }
    }
    mk = v; ml = l;
}

__device__ __forceinline__ float warp_sum(float s) {
    #pragma unroll
    for (int off = 16; off; off >>= 1)
        s += __shfl_xor_sync(0xffffffffu, s, off);
    return s;
}

// ---------------- zero scratch + transpose small weights (16384 threads) ----------
__global__ void zero_prep_kernel(const float* __restrict__ w1, const float* __restrict__ w2,
                                 const float* __restrict__ w3, const float* __restrict__ w4) {
    int i = blockIdx.x * blockDim.x + threadIdx.x;     // 0..16383
    ((unsigned int*)g_flagw)[i] = 0u;                  // BB*NN/4 == 16384
    if (i < BB * 1024) g_feat[i] = 0.0f;
    if (i < BB)        g_list_cnt[i] = 0;
    if (i < 192)  { int o = i % 64, k = i / 64;  g_tw1[k * 64 + o]  = w1[o * 3 + k]; }
    if (i < 4096) { int o = i & 63, k = i >> 6;  g_tw2[k * 64 + o]  = w2[o * 64 + k];
                                                 g_tw3[k * 64 + o]  = w3[o * 64 + k]; }
    if (i < 8192) { int o = i & 127, k = i >> 7; g_tw4[k * 128 + o] = w4[o * 64 + k]; }
}

// ---------------- FPS walk with cycle detection (1 block per batch) ----------------
__global__ __launch_bounds__(1024) void fps_kernel(const float* __restrict__ x,
                                                   const int* __restrict__ far_init) {
    const int b = blockIdx.x;
    const float* xb = x + (size_t)b * NN * 3;
    __shared__ unsigned char seen[NN];
    __shared__ float s_d[32];
    __shared__ int   s_i[32];
    __shared__ int   s_far, s_stop, s_cnt;
    const int t = threadIdx.x;

    for (int i = t; i < NN; i += 1024) seen[i] = 0;
    if (t == 0) s_cnt = 0;
    __syncthreads();

    int far = far_init[b];
    for (int it = 0; it < NC; ++it) {
        if (t == 0) {
            if (seen[far]) { s_stop = 1; }
            else { seen[far] = 1; g_cent_idx[b][s_cnt] = far; s_cnt++; s_stop = 0; }
        }
        __syncthreads();
        if (s_stop) break;
        if (it == NC - 1) break;

        const float cx = xb[far * 3 + 0], cy = xb[far * 3 + 1], cz = xb[far * 3 + 2];
        float best = -1.0f; int bi = 0;
        for (int n = t; n < NN; n += 1024) {
            float dx = xb[n * 3 + 0] - cx;
            float dy = xb[n * 3 + 1] - cy;
            float dz = xb[n * 3 + 2] - cz;
            float d = dx * dx + dy * dy + dz * dz;
            if (d > best) { best = d; bi = n; }   // strict > keeps lowest index on ties
        }
        #pragma unroll
        for (int off = 16; off; off >>= 1) {
            float d2 = __shfl_xor_sync(0xffffffffu, best, off);
            int   i2 = __shfl_xor_sync(0xffffffffu, bi, off);
            if (d2 > best || (d2 == best && i2 < bi)) { best = d2; bi = i2; }
        }
        if ((t & 31) == 0) { s_d[t >> 5] = best; s_i[t >> 5] = bi; }
        __syncthreads();
        if (t < 32) {
            best = s_d[t]; bi = s_i[t];
            #pragma unroll
            for (int off = 16; off; off >>= 1) {
                float d2 = __shfl_xor_sync(0xffffffffu, best, off);
                int   i2 = __shfl_xor_sync(0xffffffffu, bi, off);
                if (d2 > best || (d2 == best && i2 < bi)) { best = d2; bi = i2; }
            }
            if (t == 0) s_far = bi;
        }
        __syncthreads();
        far = s_far;
    }
    if (t == 0) g_cent_cnt[b] = s_cnt;
}

// ---------------- exact top-32 KNN, 32 warps per (b, centroid), merged ------------
__global__ __launch_bounds__(1024) void knn_kernel(const float* __restrict__ x) {
    const int b  = blockIdx.x >> 3;
    const int m0 = blockIdx.x & 7;
    const int cnt = g_cent_cnt[b];
    const float* xb = x + (size_t)b * NN * 3;
    __shared__ unsigned long long cand[1024];
    const int t = threadIdx.x, w = t >> 5, lane = t & 31;

    for (int m = m0; m < cnt; m += 8) {
        const int ci = g_cent_idx[b][m];
        const float cx = xb[ci * 3 + 0], cy = xb[ci * 3 + 1], cz = xb[ci * 3 + 2];
        const float cn = cx * cx + cy * cy + cz * cz;
        const int base = w * 512;

        unsigned long long key;
        {
            const int p = base + lane;
            float px = xb[p * 3 + 0], py = xb[p * 3 + 1], pz = xb[p * 3 + 2];
            float xn = px * px + py * py + pz * pz;
            float dot = cx * px + cy * py + cz * pz;
            key = dkey((cn + xn) - 2.0f * dot, p);
        }
        unsigned long long mk; int ml;
        warp_max(key, lane, mk, ml);

        for (int off = 32; off < 512; off += 32) {
            const int p = base + off + lane;
            float px = xb[p * 3 + 0], py = xb[p * 3 + 1], pz = xb[p * 3 + 2];
            float xn = px * px + py * py + pz * pz;
            float dot = cx * px + cy * py + cz * pz;
            unsigned long long k = dkey((cn + xn) - 2.0f * dot, p);
            unsigned mask = __ballot_sync(0xffffffffu, k < mk);
            while (mask) {
                const int src = __ffs(mask) - 1;
                mask &= mask - 1;
                unsigned long long kc = __shfl_sync(0xffffffffu, k, src);
                if (kc < mk) {
                    if (lane == ml) key = kc;
                    warp_max(key, lane, mk, ml);
                }
            }
        }
        cand[t] = key;
        __syncthreads();

        if (w == 0) {                       // exact merge of 1024 candidates
            key = cand[lane];
            warp_max(key, lane, mk, ml);
            for (int c = 32; c < 1024; c += 32) {
                unsigned long long k = cand[c + lane];
                unsigned mask = __ballot_sync(0xffffffffu, k < mk);
                while (mask) {
                    const int src = __ffs(mask) - 1;
                    mask &= mask - 1;
                    unsigned long long kc = __shfl_sync(0xffffffffu, k, src);
                    if (kc < mk) {
                        if (lane == ml) key = kc;
                        warp_max(key, lane, mk, ml);
                    }
                }
            }
            ((unsigned char*)g_flagw)[b * NN + (int)(key & 0xffffffffull)] = 1;
        }
        __syncthreads();
    }
}

// ---------------- compact flagged union set (vectorized flag reads) ---------------
__global__ __launch_bounds__(1024) void compact_kernel() {
    const int b = blockIdx.x, t = threadIdx.x;          // 1024 threads, 16 bytes each
    uint4 v = ((const uint4*)g_flagw[b])[t];
    unsigned vals[4] = {v.x, v.y, v.z, v.w};
    #pragma unroll
    for (int j = 0; j < 4; ++j) {
        unsigned u = vals[j];
        if (u) {
            #pragma unroll
            for (int bt = 0; bt < 4; ++bt) {
                if ((u >> (8 * bt)) & 0xffu) {
                    int pos = atomicAdd(&g_list_cnt[b], 1);
                    g_list[b][pos] = t * 16 + j * 4 + bt;
                }
            }
        }
    }
}

// ---------------- MLP phase A: 3->64->64->64->128 per point (coalesced) -----------
__global__ __launch_bounds__(128) void mlp_a_kernel(
    const float* __restrict__ x,
    const float* __restrict__ b1, const float* __restrict__ b2,
    const float* __restrict__ b3, const float* __restrict__ b4) {
    __shared__ float h1[64], h2[64], h3[64];
    const int t = threadIdx.x;

    for (int b = 0; b < BB; ++b) {
        const int cnt = g_list_cnt[b];
        for (int i = blockIdx.x; i < cnt; i += gridDim.x) {
            const int n = g_list[b][i];
            const float* p = x + ((size_t)b * NN + n) * 3;
            const float px = p[0], py = p[1], pz = p[2];

            if (t < 64) {
                float a = b1[t] + g_tw1[t] * px + g_tw1[64 + t] * py + g_tw1[128 + t] * pz;
                h1[t] = fmaxf(a, 0.0f);
            }
            __syncthreads();
            if (t < 64) {
                float a = b2[t];
                #pragma unroll 8
                for (int k = 0; k < 64; ++k) a += g_tw2[k * 64 + t] * h1[k];
                h2[t] = fmaxf(a, 0.0f);
            }
            __syncthreads();
            if (t < 64) {
                float a = b3[t];
                #pragma unroll 8
                for (int k = 0; k < 64; ++k) a += g_tw3[k * 64 + t] * h2[k];
                h3[t] = fmaxf(a, 0.0f);
            }
            __syncthreads();
            {
                float a = b4[t];
                #pragma unroll 8
                for (int k = 0; k < 64; ++k) a += g_tw4[k * 128 + t] * h3[k];
                g_h4[b][i][t] = fmaxf(a, 0.0f);
            }
            __syncthreads();
        }
    }
}

// ---------------- MLP phase B: w5 (smem tile) x h4 + relu + maxpool ---------------
#define PT 8
__global__ __launch_bounds__(64) void mlp_b_kernel(const float* __restrict__ w5,
                                                   const float* __restrict__ b5) {
    const int bid = blockIdx.x;           // BB * 16 tiles * 4 point-chunks = 256
    const int b = bid >> 6;
    const int r = bid & 63;
    const int tile = r >> 2;
    const int chunk = r & 3;
    const int o0 = tile * 64;

    __shared__ float ws[64 * 129];        // padded: conflict-free ws[t*129+k]
    __shared__ float hs[PT * 128];
    const int t = threadIdx.x;

    for (int idx = t; idx < 64 * 128; idx += 64) {
        int row = idx >> 7, k = idx & 127;
        ws[row * 129 + k] = w5[(o0 + row) * 128 + k];
    }
    const int cnt = g_list_cnt[b];
    const float bias = b5[o0 + t];
    float rmax = 0.0f;

    for (int pb = chunk * PT; pb < cnt; pb += 4 * PT) {
        const int rem = min(PT, cnt - pb);
        __syncthreads();
        for (int idx = t; idx < PT * 128; idx += 64) {
            int p = idx >> 7, k = idx & 127;
            hs[idx] = (p < rem) ? g_h4[b][pb + p][k] : 0.0f;
        }
        __syncthreads();
        float acc[PT];
        #pragma unroll
        for (int p = 0; p < PT; ++p) acc[p] = 0.0f;
        #pragma unroll 4
        for (int k = 0; k < 128; ++k) {
            const float wv = ws[t * 129 + k];
            #pragma unroll
            for (int p = 0; p < PT; ++p) acc[p] += wv * hs[p * 128 + k];
        }
        for (int p = 0; p < rem; ++p)
            rmax = fmaxf(rmax, fmaxf(acc[p] + bias, 0.0f));
    }
    atomicMax((unsigned int*)&g_feat[b * 1024 + o0 + t], __float_as_uint(rmax));
}

// ---------------- final FC head: coalesced warp-per-output, 1 block/batch ---------
__global__ __launch_bounds__(512) void fc_kernel(
    const float* __restrict__ fw1, const float* __restrict__ fb1,
    const float* __restrict__ fw2, const float* __restrict__ fb2,
    const float* __restrict__ fw3, const float* __restrict__ fb3,
    float* __restrict__ out) {
    const int b = blockIdx.x;
    __shared__ __align__(16) float g[1024];
    __shared__ __align__(16) float a1[512];
    __shared__ __align__(16) float a2[256];
    const int t = threadIdx.x, w = t >> 5, lane = t & 31;

    for (int i = t; i < 1024; i += 512) g[i] = g_feat[b * 1024 + i];
    __syncthreads();

    for (int o = w; o < 512; o += 16) {
        const float4* wr = (const float4*)(fw1 + o * 1024);
        float s = 0.0f;
        #pragma unroll
        for (int it = 0; it < 8; ++it) {
            float4 wv = wr[it * 32 + lane];
            float4 gv = *(const float4*)(g + it * 128 + lane * 4);
            s += wv.x * gv.x + wv.y * gv.y + wv.z * gv.z + wv.w * gv.w;
        }
        s = warp_sum(s);
        if (lane == 0) a1[o] = fmaxf(s + fb1[o], 0.0f);
    }
    __syncthreads();

    for (int o = w; o < 256; o += 16) {
        const float4* wr = (const float4*)(fw2 + o * 512);
        float s = 0.0f;
        #pragma unroll
        for (int it = 0; it < 4; ++it) {
            float4 wv = wr[it * 32 + lane];
            float4 av = *(const float4*)(a1 + it * 128 + lane * 4);
            s += wv.x * av.x + wv.y * av.y + wv.z * av.z + wv.w * av.w;
        }
        s = warp_sum(s);
        if (lane == 0) a2[o] = fmaxf(s + fb2[o], 0.0f);
    }
    __syncthreads();

    if (w < 3) {
        const float4* wr = (const float4*)(fw3 + w * 256);
        float s = 0.0f;
        #pragma unroll
        for (int it = 0; it < 2; ++it) {
            float4 wv = wr[it * 32 + lane];
            float4 av = *(const float4*)(a2 + it * 128 + lane * 4);
            s += wv.x * av.x + wv.y * av.y + wv.z * av.z + wv.w * av.w;
        }
        s = warp_sum(s);
        if (lane == 0) out[b * 3 + w] = s + fb3[w];
    }
}

// ---------------- launch ----------------
extern "C" void kernel_launch(void* const* d_in, const int* in_sizes, int n_in,
                              void* d_out, int out_size) {
    const float* x   = (const float*)d_in[0];
    const int*   far = (const int*)  d_in[1];
    const float* w1 = (const float*)d_in[2];   const float* b1 = (const float*)d_in[3];
    const float* w2 = (const float*)d_in[4];   const float* b2 = (const float*)d_in[5];
    const float* w3 = (const float*)d_in[6];   const float* b3 = (const float*)d_in[7];
    const float* w4 = (const float*)d_in[8];   const float* b4 = (const float*)d_in[9];
    const float* w5 = (const float*)d_in[10];  const float* b5 = (const float*)d_in[11];
    const float* fw1 = (const float*)d_in[12]; const float* fb1 = (const float*)d_in[13];
    const float* fw2 = (const float*)d_in[14]; const float* fb2 = (const float*)d_in[15];
    const float* fw3 = (const float*)d_in[16]; const float* fb3 = (const float*)d_in[17];
    float* out = (float*)d_out;

    zero_prep_kernel<<<64, 256>>>(w1, w2, w3, w4);
    fps_kernel<<<BB, 1024>>>(x, far);
    knn_kernel<<<BB * 8, 1024>>>(x);
    compact_kernel<<<BB, 1024>>>();
    mlp_a_kernel<<<64, 128>>>(x, b1, b2, b3, b4);
    mlp_b_kernel<<<BB * 64, 64>>>(w5, b5);
    fc_kernel<<<BB, 512>>>(fw1, fb1, fw2, fb2, fw3, fb3, out);
}

// round 5
// speedup vs baseline: 14.4875x; 1.3020x over previous
#include <cuda_runtime.h>

#define BB 4
#define NN 16384
#define NC 1024

// ---------------- scratch (device globals; no allocation allowed) ----------------
__device__ unsigned int g_flagbits[BB][NN / 32];
__device__ int          g_list[BB][NN];
__device__ int          g_list_cnt[BB];
__device__ float        g_feat[BB * 1024];           // max-pooled (relu'd) features
__device__ float        g_h4[BB][NN][128];           // per-point layer-4 activations
__device__ float        g_a1[BB][512];               // fc layer-1 activations
__device__ float        g_tw1[3 * 64];               // transposed small weights
__device__ float        g_tw2[64 * 64];
__device__ float        g_tw3[64 * 64];
__device__ float        g_tw4[64 * 128];

// ---------------- helpers ----------------
__device__ __forceinline__ unsigned long long dkey(float d, int idx) {
    unsigned u = __float_as_uint(d);
    u = (u & 0x80000000u) ? ~u : (u | 0x80000000u);   // ascending-sortable
    return ((unsigned long long)u << 32) | (unsigned)idx;
}

__device__ __forceinline__ void warp_max(unsigned long long key, int lane,
                                         unsigned long long& mk, int& ml) {
    unsigned long long v = key; int l = lane;
    #pragma unroll
    for (int off = 16; off; off >>= 1) {
        unsigned long long v2 = __shfl_xor_sync(0xffffffffu, v, off);
        int l2 = __shfl_xor_sync(0xffffffffu, l, off);
        if (v2 > v) { v = v2; l = l2; }
    }
    mk = v; ml = l;
}

__device__ __forceinline__ float warp_sum(float s) {
    #pragma unroll
    for (int off = 16; off; off >>= 1)
        s += __shfl_xor_sync(0xffffffffu, s, off);
    return s;
}

// ---------------- zero scratch + transpose small weights --------------------------
__global__ void prep_kernel(const float* __restrict__ w1, const float* __restrict__ w2,
                            const float* __restrict__ w3, const float* __restrict__ w4) {
    int i = blockIdx.x * blockDim.x + threadIdx.x;     // 8192 threads
    if (i < BB * NN / 32) ((unsigned*)g_flagbits)[i] = 0u;   // 2048 words
    if (i < BB * 1024)    g_feat[i] = 0.0f;
    if (i < BB)           g_list_cnt[i] = 0;
    if (i < 192)  { int o = i % 64, k = i / 64;  g_tw1[k * 64 + o]  = w1[o * 3 + k]; }
    if (i < 4096) { int o = i & 63, k = i >> 6;  g_tw2[k * 64 + o]  = w2[o * 64 + k];
                                                 g_tw3[k * 64 + o]  = w3[o * 64 + k]; }
    if (i < 8192) { int o = i & 127, k = i >> 7; g_tw4[k * 128 + o] = w4[o * 64 + k]; }
}

// ---------------- fused FPS walk + exact top-32 KNN + dedup list append -----------
// BB*8 blocks of 1024. Each block stages its batch into smem SoA + registers,
// redundantly runs the (cheap) FPS walk, then handles centroids m0, m0+8, ...
__global__ __launch_bounds__(1024) void fpsknn_kernel(const float* __restrict__ x,
                                                      const int* __restrict__ far_init) {
    extern __shared__ float dsm[];
    float* sx = dsm;
    float* sy = sx + NN;
    float* sz = sy + NN;
    unsigned long long* cand = (unsigned long long*)(sz + NN);
    __shared__ unsigned s_seen[NN / 32];
    __shared__ int s_cent[NC];
    __shared__ float s_d[32];
    __shared__ int   s_i[32];
    __shared__ int   s_far, s_stop, s_cnt;

    const int b = blockIdx.x >> 3, m0 = blockIdx.x & 7;
    const float* xb = x + (size_t)b * NN * 3;
    const int t = threadIdx.x, w = t >> 5, lane = t & 31;

    float rx[16], ry[16], rz[16];
    #pragma unroll
    for (int j = 0; j < 16; ++j) {
        const int i = t + j * 1024;
        float a = xb[i * 3 + 0], bb = xb[i * 3 + 1], c = xb[i * 3 + 2];
        sx[i] = a; sy[i] = bb; sz[i] = c;
        rx[j] = a; ry[j] = bb; rz[j] = c;
    }
    if (t < NN / 32) s_seen[t] = 0;
    if (t == 0) s_cnt = 0;
    __syncthreads();

    // ---- FPS walk with cycle detection (points held in registers) ----
    int far = far_init[b];
    for (int it = 0; it < NC; ++it) {
        if (t == 0) {
            const unsigned wd = (unsigned)far >> 5, bt = 1u << (far & 31);
            if (s_seen[wd] & bt) { s_stop = 1; }
            else { s_seen[wd] |= bt; s_cent[s_cnt++] = far; s_stop = 0; }
        }
        __syncthreads();
        if (s_stop) break;
        if (it == NC - 1) break;

        const float cx = sx[far], cy = sy[far], cz = sz[far];
        float best = -1.0f; int bi = 0;
        #pragma unroll
        for (int j = 0; j < 16; ++j) {
            float dx = rx[j] - cx, dy = ry[j] - cy, dz = rz[j] - cz;
            float d = dx * dx + dy * dy + dz * dz;
            if (d > best) { best = d; bi = t + j * 1024; }   // strict >: lowest idx on tie
        }
        #pragma unroll
        for (int off = 16; off; off >>= 1) {
            float d2 = __shfl_xor_sync(0xffffffffu, best, off);
            int   i2 = __shfl_xor_sync(0xffffffffu, bi, off);
            if (d2 > best || (d2 == best && i2 < bi)) { best = d2; bi = i2; }
        }
        if (lane == 0) { s_d[w] = best; s_i[w] = bi; }
        __syncthreads();
        if (t < 32) {
            best = s_d[t]; bi = s_i[t];
            #pragma unroll
            for (int off = 16; off; off >>= 1) {
                float d2 = __shfl_xor_sync(0xffffffffu, best, off);
                int   i2 = __shfl_xor_sync(0xffffffffu, bi, off);
                if (d2 > best || (d2 == best && i2 < bi)) { best = d2; bi = i2; }
            }
            if (t == 0) s_far = bi;
        }
        __syncthreads();
        far = s_far;
    }
    __syncthreads();

    // ---- exact top-32 KNN from smem SoA, 32 warps per centroid ----
    const int cnt = s_cnt;
    for (int m = m0; m < cnt; m += 8) {
        const int ci = s_cent[m];
        const float cx = sx[ci], cy = sy[ci], cz = sz[ci];
        const float cn = cx * cx + cy * cy + cz * cz;
        const int base = w * 512;

        unsigned long long key;
        {
            const int p = base + lane;
            float px = sx[p], py = sy[p], pz = sz[p];
            float xn = px * px + py * py + pz * pz;
            float dot = cx * px + cy * py + cz * pz;
            key = dkey((cn + xn) - 2.0f * dot, p);
        }
        unsigned long long mk; int ml;
        warp_max(key, lane, mk, ml);

        for (int off = 32; off < 512; off += 32) {
            const int p = base + off + lane;
            float px = sx[p], py = sy[p], pz = sz[p];
            float xn = px * px + py * py + pz * pz;
            float dot = cx * px + cy * py + cz * pz;
            unsigned long long k = dkey((cn + xn) - 2.0f * dot, p);
            unsigned mask = __ballot_sync(0xffffffffu, k < mk);
            while (mask) {
                const int src = __ffs(mask) - 1;
                mask &= mask - 1;
                unsigned long long kc = __shfl_sync(0xffffffffu, k, src);
                if (kc < mk) {
                    if (lane == ml) key = kc;
                    warp_max(key, lane, mk, ml);
                }
            }
        }
        cand[t] = key;
        __syncthreads();

        if (w == 0) {                       // exact merge of 1024 candidates
            key = cand[lane];
            warp_max(key, lane, mk, ml);
            for (int c = 32; c < 1024; c += 32) {
                unsigned long long k = cand[c + lane];
                unsigned mask = __ballot_sync(0xffffffffu, k < mk);
                while (mask) {
                    const int src = __ffs(mask) - 1;
                    mask &= mask - 1;
                    unsigned long long kc = __shfl_sync(0xffffffffu, k, src);
                    if (kc < mk) {
                        if (lane == ml) key = kc;
                        warp_max(key, lane, mk, ml);
                    }
                }
            }
            // dedup append to union list
            const int n = (int)(key & 0xffffffffull);
            const unsigned bt = 1u << (n & 31);
            unsigned old = atomicOr(&g_flagbits[b][(unsigned)n >> 5], bt);
            if (!(old & bt)) {
                int pos = atomicAdd(&g_list_cnt[b], 1);
                g_list[b][pos] = n;
            }
        }
        __syncthreads();
    }
}

// ---------------- MLP phase A: 3->64->64->64->128 per point (coalesced) -----------
__global__ __launch_bounds__(128) void mlp_a_kernel(
    const float* __restrict__ x,
    const float* __restrict__ b1, const float* __restrict__ b2,
    const float* __restrict__ b3, const float* __restrict__ b4) {
    __shared__ float h1[64], h2[64], h3[64];
    const int t = threadIdx.x;

    for (int b = 0; b < BB; ++b) {
        const int cnt = g_list_cnt[b];
        for (int i = blockIdx.x; i < cnt; i += gridDim.x) {
            const int n = g_list[b][i];
            const float* p = x + ((size_t)b * NN + n) * 3;
            const float px = p[0], py = p[1], pz = p[2];

            if (t < 64) {
                float a = b1[t] + g_tw1[t] * px + g_tw1[64 + t] * py + g_tw1[128 + t] * pz;
                h1[t] = fmaxf(a, 0.0f);
            }
            __syncthreads();
            if (t < 64) {
                float a0 = 0.f, a1 = 0.f, a2 = 0.f, a3 = 0.f;
                #pragma unroll
                for (int k = 0; k < 64; k += 4) {
                    a0 += g_tw2[(k + 0) * 64 + t] * h1[k + 0];
                    a1 += g_tw2[(k + 1) * 64 + t] * h1[k + 1];
                    a2 += g_tw2[(k + 2) * 64 + t] * h1[k + 2];
                    a3 += g_tw2[(k + 3) * 64 + t] * h1[k + 3];
                }
                h2[t] = fmaxf(b2[t] + ((a0 + a1) + (a2 + a3)), 0.0f);
            }
            __syncthreads();
            if (t < 64) {
                float a0 = 0.f, a1 = 0.f, a2 = 0.f, a3 = 0.f;
                #pragma unroll
                for (int k = 0; k < 64; k += 4) {
                    a0 += g_tw3[(k + 0) * 64 + t] * h2[k + 0];
                    a1 += g_tw3[(k + 1) * 64 + t] * h2[k + 1];
                    a2 += g_tw3[(k + 2) * 64 + t] * h2[k + 2];
                    a3 += g_tw3[(k + 3) * 64 + t] * h2[k + 3];
                }
                h3[t] = fmaxf(b3[t] + ((a0 + a1) + (a2 + a3)), 0.0f);
            }
            __syncthreads();
            {
                float a0 = 0.f, a1 = 0.f, a2 = 0.f, a3 = 0.f;
                #pragma unroll
                for (int k = 0; k < 64; k += 4) {
                    a0 += g_tw4[(k + 0) * 128 + t] * h3[k + 0];
                    a1 += g_tw4[(k + 1) * 128 + t] * h3[k + 1];
                    a2 += g_tw4[(k + 2) * 128 + t] * h3[k + 2];
                    a3 += g_tw4[(k + 3) * 128 + t] * h3[k + 3];
                }
                g_h4[b][i][t] = fmaxf(b4[t] + ((a0 + a1) + (a2 + a3)), 0.0f);
            }
            __syncthreads();
        }
    }
}

// ---------------- MLP phase B: w5 (smem tile) x h4 + relu + maxpool ---------------
#define PT 8
__global__ __launch_bounds__(64) void mlp_b_kernel(const float* __restrict__ w5,
                                                   const float* __restrict__ b5) {
    const int bid = blockIdx.x;           // BB * 16 tiles * 4 point-chunks = 256
    const int b = bid >> 6;
    const int r = bid & 63;
    const int tile = r >> 2;
    const int chunk = r & 3;
    const int o0 = tile * 64;

    __shared__ float ws[64 * 129];        // padded: conflict-free ws[t*129+k]
    __shared__ float hs[PT * 128];
    const int t = threadIdx.x;

    for (int idx = t; idx < 64 * 128; idx += 64) {
        int row = idx >> 7, k = idx & 127;
        ws[row * 129 + k] = w5[(o0 + row) * 128 + k];
    }
    const int cnt = g_list_cnt[b];
    const float bias = b5[o0 + t];
    float rmax = 0.0f;

    for (int pb = chunk * PT; pb < cnt; pb += 4 * PT) {
        const int rem = min(PT, cnt - pb);
        __syncthreads();
        for (int idx = t; idx < PT * 128; idx += 64) {
            int p = idx >> 7, k = idx & 127;
            hs[idx] = (p < rem) ? g_h4[b][pb + p][k] : 0.0f;
        }
        __syncthreads();
        float acc[PT];
        #pragma unroll
        for (int p = 0; p < PT; ++p) acc[p] = 0.0f;
        #pragma unroll 4
        for (int k = 0; k < 128; ++k) {
            const float wv = ws[t * 129 + k];
            #pragma unroll
            for (int p = 0; p < PT; ++p) acc[p] += wv * hs[p * 128 + k];
        }
        for (int p = 0; p < rem; ++p)
            rmax = fmaxf(rmax, fmaxf(acc[p] + bias, 0.0f));
    }
    atomicMax((unsigned int*)&g_feat[b * 1024 + o0 + t], __float_as_uint(rmax));
}

// ---------------- FC layer 1 (1024->512), 16 blocks per batch ---------------------
__global__ __launch_bounds__(256) void fc1_kernel(const float* __restrict__ fw1,
                                                  const float* __restrict__ fb1) {
    const int b = blockIdx.x >> 4, seg = blockIdx.x & 15;
    __shared__ __align__(16) float g[1024];
    const int t = threadIdx.x, w = t >> 5, lane = t & 31;

    for (int i = t; i < 1024; i += 256) g[i] = g_feat[b * 1024 + i];
    __syncthreads();

    #pragma unroll
    for (int q = 0; q < 4; ++q) {
        const int o = seg * 32 + w * 4 + q;
        const float4* wr = (const float4*)(fw1 + o * 1024);
        float s = 0.0f;
        #pragma unroll
        for (int it = 0; it < 8; ++it) {
            float4 wv = wr[it * 32 + lane];
            float4 gv = *(const float4*)(g + it * 128 + lane * 4);
            s += wv.x * gv.x + wv.y * gv.y + wv.z * gv.z + wv.w * gv.w;
        }
        s = warp_sum(s);
        if (lane == 0) g_a1[b][o] = fmaxf(s + fb1[o], 0.0f);
    }
}

// ---------------- FC layers 2+3 (512->256->3), 1 block per batch ------------------
__global__ __launch_bounds__(256) void fc2_kernel(
    const float* __restrict__ fw2, const float* __restrict__ fb2,
    const float* __restrict__ fw3, const float* __restrict__ fb3,
    float* __restrict__ out) {
    const int b = blockIdx.x;
    __shared__ __align__(16) float a1[512];
    __shared__ __align__(16) float a2[256];
    const int t = threadIdx.x, w = t >> 5, lane = t & 31;

    for (int i = t; i < 512; i += 256) a1[i] = g_a1[b][i];
    __syncthreads();

    {
        const int o = w * 32;   // each warp: 32 consecutive outputs
        for (int j = 0; j < 32; ++j) {
            const float4* wr = (const float4*)(fw2 + (o + j) * 512);
            float s = 0.0f;
            #pragma unroll
            for (int it = 0; it < 4; ++it) {
                float4 wv = wr[it * 32 + lane];
                float4 av = *(const float4*)(a1 + it * 128 + lane * 4);
                s += wv.x * av.x + wv.y * av.y + wv.z * av.z + wv.w * av.w;
            }
            s = warp_sum(s);
            if (lane == 0) a2[o + j] = fmaxf(s + fb2[o + j], 0.0f);
        }
    }
    __syncthreads();

    if (w < 3) {
        const float4* wr = (const float4*)(fw3 + w * 256);
        float s = 0.0f;
        #pragma unroll
        for (int it = 0; it < 2; ++it) {
            float4 wv = wr[it * 32 + lane];
            float4 av = *(const float4*)(a2 + it * 128 + lane * 4);
            s += wv.x * av.x + wv.y * av.y + wv.z * av.z + wv.w * av.w;
        }
        s = warp_sum(s);
        if (lane == 0) out[b * 3 + w] = s + fb3[w];
    }
}

// ---------------- launch ----------------
extern "C" void kernel_launch(void* const* d_in, const int* in_sizes, int n_in,
                              void* d_out, int out_size) {
    const float* x   = (const float*)d_in[0];
    const int*   far = (const int*)  d_in[1];
    const float* w1 = (const float*)d_in[2];   const float* b1 = (const float*)d_in[3];
    const float* w2 = (const float*)d_in[4];   const float* b2 = (const float*)d_in[5];
    const float* w3 = (const float*)d_in[6];   const float* b3 = (const float*)d_in[7];
    const float* w4 = (const float*)d_in[8];   const float* b4 = (const float*)d_in[9];
    const float* w5 = (const float*)d_in[10];  const float* b5 = (const float*)d_in[11];
    const float* fw1 = (const float*)d_in[12]; const float* fb1 = (const float*)d_in[13];
    const float* fw2 = (const float*)d_in[14]; const float* fb2 = (const float*)d_in[15];
    const float* fw3 = (const float*)d_in[16]; const float* fb3 = (const float*)d_in[17];
    float* out = (float*)d_out;

    const int smem_bytes = 3 * NN * 4 + 1024 * 8;   // SoA + merge candidates = 204800
    static int attr_set = 0;
    if (!attr_set) {
        cudaFuncSetAttribute(fpsknn_kernel,
                             cudaFuncAttributeMaxDynamicSharedMemorySize, smem_bytes);
        attr_set = 1;
    }

    prep_kernel<<<32, 256>>>(w1, w2, w3, w4);
    fpsknn_kernel<<<BB * 8, 1024, smem_bytes>>>(x, far);
    mlp_a_kernel<<<128, 128>>>(x, b1, b2, b3, b4);
    mlp_b_kernel<<<BB * 64, 64>>>(w5, b5);
    fc1_kernel<<<BB * 16, 256>>>(fw1, fb1);
    fc2_kernel<<<BB, 256>>>(fw2, fb2, fw3, fb3, out);
}